// round 4
// baseline (speedup 1.0000x reference)
#include <cuda_runtime.h>
#include <cstdint>

#define NB    4096
#define KCH   3
#define FIN   16
#define FOUT  16
#define TT    12
#define BATCH 2
#define COLS  384                       /* BATCH*FOUT*TT */
#define OUT_ELEMS (BATCH*NB*FOUT*TT)    /* 1572864 */

#define BM 128
#define BN 128
#define BKK 32
#define NSTEPS (NB/BKK)                 /* 128 */
#define A_PAD 136
#define B_PAD 36
#define AS_FLOATS (BKK*A_PAD)                 /* 4352 */
#define BS_FLOATS (BN*B_PAD)                  /* 4608 */
#define STAGE_FLOATS (AS_FLOATS + BS_FLOATS)  /* 8960 -> 35840 B */
#define STAGES 3
#define SMEM_BYTES (STAGES*STAGE_FLOATS*4)    /* 107520 */

__device__ float g_lhs[KCH*FIN*FOUT];
__device__ float g_zT[(size_t)KCH*COLS*NB];     // [k][col][m], m contiguous (tf32-rounded)
__device__ float g_part[(size_t)KCH*NB*COLS];   // [k][n][col]

// ---------------------------------------------------------------------------
__device__ __forceinline__ uint32_t smem_u32(const void* p) {
    uint32_t a;
    asm("{ .reg .u64 t; cvta.to.shared.u64 t, %1; cvt.u32.u64 %0, t; }" : "=r"(a) : "l"(p));
    return a;
}
#define CPASYNC16(d, s) asm volatile("cp.async.cg.shared.global [%0], [%1], 16;" :: "r"(d), "l"(s) : "memory")
#define CP_COMMIT()     asm volatile("cp.async.commit_group;" ::: "memory")

__device__ __forceinline__ void mma_tf32(float* c, const uint32_t* a, const uint32_t* b) {
    asm volatile(
        "mma.sync.aligned.m16n8k8.row.col.f32.tf32.tf32.f32 "
        "{%0,%1,%2,%3}, {%4,%5,%6,%7}, {%8,%9}, {%0,%1,%2,%3};"
        : "+f"(c[0]), "+f"(c[1]), "+f"(c[2]), "+f"(c[3])
        : "r"(a[0]), "r"(a[1]), "r"(a[2]), "r"(a[3]), "r"(b[0]), "r"(b[1]));
}
__device__ __forceinline__ uint32_t to_tf32(float f) {
    uint32_t u; asm("cvt.rna.tf32.f32 %0, %1;" : "=r"(u) : "f"(f)); return u;
}

// ---------------------------------------------------------------------------
// lhs[k,f,o] = 0.5 * sum_j Gamma[j,f,o] * xj[j,k]
// ---------------------------------------------------------------------------
__global__ void lhs_kernel(const float* __restrict__ Gamma, const float* __restrict__ xj) {
    int idx = blockIdx.x * blockDim.x + threadIdx.x;
    if (idx < KCH*FIN*FOUT) {
        int k = idx / (FIN*FOUT), fo = idx % (FIN*FOUT);
        float s = 0.f;
#pragma unroll
        for (int j = 0; j < KCH; ++j) s += Gamma[j*FIN*FOUT + fo] * xj[j*KCH + k];
        g_lhs[idx] = 0.5f * s;
    }
}

// ---------------------------------------------------------------------------
// zT[k][col=b*192+o*12+t][m] = rn_tf32( sum_f x[b,m,f,t] * lhs[k,f,o] )
// ---------------------------------------------------------------------------
__global__ void zT_kernel(const float* __restrict__ x) {
    __shared__ float ls[KCH*FIN*FOUT];
    const int tid = threadIdx.x;
    const int mc = blockIdx.x, t = blockIdx.y, b = blockIdx.z;
    for (int i = tid; i < KCH*FIN*FOUT; i += 128) ls[i] = g_lhs[i];
    __syncthreads();
    const int m = mc * 128 + tid;
    float xv[FIN];
    const float* xp = x + ((size_t)(b*NB + m) * FIN) * TT + t;
#pragma unroll
    for (int f = 0; f < FIN; ++f) xv[f] = xp[f*TT];
#pragma unroll
    for (int k = 0; k < KCH; ++k)
#pragma unroll
        for (int o = 0; o < FOUT; ++o) {
            float s = 0.f;
#pragma unroll
            for (int f = 0; f < FIN; ++f) s += xv[f] * ls[(k*FIN + f)*FOUT + o];
            g_zT[((size_t)k*COLS + b*(FOUT*TT) + o*TT + t) * NB + m] = __uint_as_float(to_tf32(s));
        }
}

// ---------------------------------------------------------------------------
// GEMM: g_part[kb][n][col] = sum_m cheb[kb][m][n] * zT[kb][col][m]
// mma.sync tf32, 128x128x32 block tile, 64x64 warp tile (4 warps),
// 3-stage cp.async pipeline.
// ---------------------------------------------------------------------------
__global__ void __launch_bounds__(128, 2) gemm_kernel(const float* __restrict__ cheb) {
    extern __shared__ float sm[];
    const int tid  = threadIdx.x;
    const int lane = tid & 31, wid = tid >> 5;
    const int warp_m = wid >> 1, warp_n = wid & 1;      // 2x2 warp grid
    const int n0 = blockIdx.x * BM;
    const int c0 = blockIdx.y * BN;
    const int kb = blockIdx.z;

    const float* Ag = cheb + (size_t)kb*NB*NB + n0;              // + m*NB
    const float* Bg = g_zT + (size_t)kb*COLS*NB + (size_t)c0*NB; // + col*NB + m

    // ---- stage loader: A[m][n] (32 x 128), B[col][m] (128 x 32); 16 cp/thread
    auto load_stage = [&](int stage, int m0) {
        float* As = sm + stage * STAGE_FLOATS;
        float* Bs = As + AS_FLOATS;
#pragma unroll
        for (int j = 0; j < 8; ++j) {
            int i = tid + 128*j;
            int m = i >> 5, c = i & 31;
            CPASYNC16(smem_u32(As + m*A_PAD + c*4), Ag + (size_t)(m0 + m)*NB + c*4);
        }
#pragma unroll
        for (int j = 0; j < 8; ++j) {
            int i = tid + 128*j;
            int col = i >> 3, ch = i & 7;
            CPASYNC16(smem_u32(Bs + col*B_PAD + ch*4), Bg + (size_t)col*NB + m0 + ch*4);
        }
    };

    load_stage(0, 0);       CP_COMMIT();
    load_stage(1, BKK);     CP_COMMIT();
    load_stage(2, 2*BKK);   CP_COMMIT();

    float acc[4][8][4];
#pragma unroll
    for (int mi = 0; mi < 4; ++mi)
#pragma unroll
        for (int ni = 0; ni < 8; ++ni)
#pragma unroll
            for (int q = 0; q < 4; ++q) acc[mi][ni][q] = 0.f;

    const int nb0 = warp_m * 64;
    const int cb0 = warp_n * 64;
    const int r4  = lane >> 2;   // 0..7
    const int l4  = lane & 3;    // 0..3

    int buf = 0;
    for (int it = 0; it < NSTEPS; ++it) {
        asm volatile("cp.async.wait_group 2;" ::: "memory");
        __syncthreads();
        const float* As = sm + buf * STAGE_FLOATS;
        const float* Bs = As + AS_FLOATS;
#pragma unroll
        for (int ks = 0; ks < 4; ++ks) {
            const int mm = ks * 8 + l4;
            uint32_t a[4][4];
#pragma unroll
            for (int mi = 0; mi < 4; ++mi) {
                const int nb = nb0 + mi*16 + r4;
                a[mi][0] = to_tf32(As[ mm      *A_PAD + nb    ]);
                a[mi][1] = to_tf32(As[ mm      *A_PAD + nb + 8]);
                a[mi][2] = to_tf32(As[(mm + 4) *A_PAD + nb    ]);
                a[mi][3] = to_tf32(As[(mm + 4) *A_PAD + nb + 8]);
            }
            uint32_t b[8][2];
#pragma unroll
            for (int ni = 0; ni < 8; ++ni) {
                const int cc = cb0 + ni*8 + r4;
                b[ni][0] = __float_as_uint(Bs[cc*B_PAD + mm    ]);
                b[ni][1] = __float_as_uint(Bs[cc*B_PAD + mm + 4]);
            }
#pragma unroll
            for (int mi = 0; mi < 4; ++mi)
#pragma unroll
                for (int ni = 0; ni < 8; ++ni)
                    mma_tf32(acc[mi][ni], a[mi], b[ni]);
        }
        __syncthreads();
        if (it + 3 < NSTEPS) load_stage(buf, (it + 3) * BKK);
        CP_COMMIT();
        buf = (buf == 2) ? 0 : buf + 1;
    }

    // ---- epilogue: per-k partials
    float* P = g_part + (size_t)kb*NB*COLS;
#pragma unroll
    for (int mi = 0; mi < 4; ++mi) {
        const int row0 = n0 + nb0 + mi*16 + r4;
#pragma unroll
        for (int ni = 0; ni < 8; ++ni) {
            const int col = c0 + cb0 + ni*8 + 2*l4;
            *(float2*)&P[(size_t) row0      *COLS + col] = make_float2(acc[mi][ni][0], acc[mi][ni][1]);
            *(float2*)&P[(size_t)(row0 + 8) *COLS + col] = make_float2(acc[mi][ni][2], acc[mi][ni][3]);
        }
    }
}

// ---------------------------------------------------------------------------
// out = relu( sum_kb g_part ), vectorized float4
// out[b][n][c], c in [0,192): out4 idx = (b*NB + n)*48 + c4
// g_part[kb][n][b*192 + c] -> part4[(kb*NB + n)*96 + b*48 + c4]
// ---------------------------------------------------------------------------
__global__ void relu_sum_kernel(float4* __restrict__ out) {
    int idx = blockIdx.x * blockDim.x + threadIdx.x;      // 0 .. OUT_ELEMS/4
    if (idx < OUT_ELEMS/4) {
        int b  = idx / (NB*48);
        int r  = idx % (NB*48);
        int n  = r / 48;
        int c4 = r % 48;
        const float4* p = (const float4*)g_part;
        size_t off = (size_t)n*96 + b*48 + c4;
        float4 v0 = p[off];
        float4 v1 = p[(size_t)NB*96 + off];
        float4 v2 = p[2*(size_t)NB*96 + off];
        float4 o;
        o.x = fmaxf(v0.x + v1.x + v2.x, 0.f);
        o.y = fmaxf(v0.y + v1.y + v2.y, 0.f);
        o.z = fmaxf(v0.z + v1.z + v2.z, 0.f);
        o.w = fmaxf(v0.w + v1.w + v2.w, 0.f);
        out[idx] = o;
    }
}

// ---------------------------------------------------------------------------
extern "C" void kernel_launch(void* const* d_in, const int* in_sizes, int n_in,
                              void* d_out, int out_size) {
    const float* x     = (const float*)d_in[0];
    const float* cheb  = (const float*)d_in[1];
    const float* xj    = (const float*)d_in[2];
    const float* Gamma = (const float*)d_in[3];

    cudaFuncSetAttribute(gemm_kernel, cudaFuncAttributeMaxDynamicSharedMemorySize, SMEM_BYTES);

    lhs_kernel<<<3, 256>>>(Gamma, xj);
    zT_kernel<<<dim3(32, 12, 2), 128>>>(x);
    gemm_kernel<<<dim3(32, 3, 3), 128, SMEM_BYTES>>>(cheb);
    relu_sum_kernel<<<(OUT_ELEMS/4 + 255)/256, 256>>>((float4*)d_out);
}

// round 5
// speedup vs baseline: 1.3873x; 1.3873x over previous
#include <cuda_runtime.h>
#include <cuda_fp16.h>
#include <cstdint>

#define NB    4096
#define KCH   3
#define FIN   16
#define FOUT  16
#define TT    12
#define BATCH 2
#define COLS  384                       /* BATCH*FOUT*TT */
#define OUT_ELEMS (BATCH*NB*FOUT*TT)    /* 1572864 */

#define BM 128
#define BN 128
#define BKK 32
#define NSTEPS (NB/BKK)                 /* 128 */
#define A_PAD 132                       /* floats per A smem row (528B, 16B aligned, 4 mod 32) */
#define B_PADH 40                       /* halves per B smem row (80B, 16B aligned) */
#define AS_BYTES (BKK*A_PAD*4)          /* 16896 */
#define BS_BYTES (BN*B_PADH*2)          /* 10240 */
#define STAGE_BYTES (AS_BYTES + BS_BYTES) /* 27136 */
#define STAGES 3
#define SMEM_BYTES (STAGES*STAGE_BYTES)   /* 81408 */

__device__ float  g_lhs[KCH*FIN*FOUT];
__device__ __half g_zTh[(size_t)KCH*COLS*NB];   // [k][col][m], m contiguous, fp16
__device__ float  g_part[(size_t)KCH*NB*COLS];  // [k][n][col]

// ---------------------------------------------------------------------------
__device__ __forceinline__ uint32_t smem_u32(const void* p) {
    uint32_t a;
    asm("{ .reg .u64 t; cvta.to.shared.u64 t, %1; cvt.u32.u64 %0, t; }" : "=r"(a) : "l"(p));
    return a;
}
#define CPASYNC16(d, s) asm volatile("cp.async.cg.shared.global [%0], [%1], 16;" :: "r"(d), "l"(s) : "memory")
#define CP_COMMIT()     asm volatile("cp.async.commit_group;" ::: "memory")

__device__ __forceinline__ void mma_f16(float* c, const uint32_t* a, const uint32_t* b) {
    asm volatile(
        "mma.sync.aligned.m16n8k16.row.col.f32.f16.f16.f32 "
        "{%0,%1,%2,%3}, {%4,%5,%6,%7}, {%8,%9}, {%0,%1,%2,%3};"
        : "+f"(c[0]), "+f"(c[1]), "+f"(c[2]), "+f"(c[3])
        : "r"(a[0]), "r"(a[1]), "r"(a[2]), "r"(a[3]), "r"(b[0]), "r"(b[1]));
}
// pack two f32 into f16x2: low half = lo, high half = hi
__device__ __forceinline__ uint32_t packh(float lo, float hi) {
    uint32_t r;
    asm("cvt.rn.f16x2.f32 %0, %1, %2;" : "=r"(r) : "f"(hi), "f"(lo));
    return r;
}

// ---------------------------------------------------------------------------
// lhs[k,f,o] = 0.5 * sum_j Gamma[j,f,o] * xj[j,k]
// ---------------------------------------------------------------------------
__global__ void lhs_kernel(const float* __restrict__ Gamma, const float* __restrict__ xj) {
    int idx = blockIdx.x * blockDim.x + threadIdx.x;
    if (idx < KCH*FIN*FOUT) {
        int k = idx / (FIN*FOUT), fo = idx % (FIN*FOUT);
        float s = 0.f;
#pragma unroll
        for (int j = 0; j < KCH; ++j) s += Gamma[j*FIN*FOUT + fo] * xj[j*KCH + k];
        g_lhs[idx] = 0.5f * s;
    }
}

// ---------------------------------------------------------------------------
// zTh[k][col=b*192+o*12+t][m] = fp16( sum_f x[b,m,f,t] * lhs[k,f,o] )
// ---------------------------------------------------------------------------
__global__ void zT_kernel(const float* __restrict__ x) {
    __shared__ float ls[KCH*FIN*FOUT];
    const int tid = threadIdx.x;
    const int mc = blockIdx.x, t = blockIdx.y, b = blockIdx.z;
    for (int i = tid; i < KCH*FIN*FOUT; i += 128) ls[i] = g_lhs[i];
    __syncthreads();
    const int m = mc * 128 + tid;
    float xv[FIN];
    const float* xp = x + ((size_t)(b*NB + m) * FIN) * TT + t;
#pragma unroll
    for (int f = 0; f < FIN; ++f) xv[f] = xp[f*TT];
#pragma unroll
    for (int k = 0; k < KCH; ++k)
#pragma unroll
        for (int o = 0; o < FOUT; ++o) {
            float s = 0.f;
#pragma unroll
            for (int f = 0; f < FIN; ++f) s += xv[f] * ls[(k*FIN + f)*FOUT + o];
            g_zTh[((size_t)k*COLS + b*(FOUT*TT) + o*TT + t) * NB + m] = __float2half_rn(s);
        }
}

// ---------------------------------------------------------------------------
// GEMM: g_part[kb][n][col] = sum_m cheb[kb][m][n] * zTh[kb][col][m]
// fp16 mma.sync m16n8k16, 128x128x32 block tile, 64x64 warp tile (4 warps),
// 3-stage cp.async pipeline. A (cheb) fp32 in smem -> cvt.f16x2 in-register.
// ---------------------------------------------------------------------------
__global__ void __launch_bounds__(128, 2) gemm_kernel(const float* __restrict__ cheb) {
    extern __shared__ char smc[];
    const int tid  = threadIdx.x;
    const int lane = tid & 31, wid = tid >> 5;
    const int warp_m = wid >> 1, warp_n = wid & 1;      // 2x2 warp grid
    const int n0 = blockIdx.x * BM;
    const int c0 = blockIdx.y * BN;
    const int kb = blockIdx.z;

    const float*  Ag = cheb  + (size_t)kb*NB*NB + n0;              // + m*NB
    const __half* Bg = g_zTh + (size_t)kb*COLS*NB + (size_t)c0*NB; // + col*NB + m

    // ---- stage loader: A fp32 [32m x 128n], B fp16 [128col x 32m]
    auto load_stage = [&](int stage, int m0) {
        char* Sa = smc + stage * STAGE_BYTES;
        char* Sb = Sa + AS_BYTES;
#pragma unroll
        for (int j = 0; j < 8; ++j) {
            int i = tid + 128*j;
            int m = i >> 5, c = i & 31;                  // c: 16B chunk (4 floats)
            CPASYNC16(smem_u32(Sa + (m*A_PAD + c*4)*4), Ag + (size_t)(m0 + m)*NB + c*4);
        }
#pragma unroll
        for (int j = 0; j < 4; ++j) {
            int i = tid + 128*j;
            int col = i >> 2, ch = i & 3;                // ch: 16B chunk (8 halves)
            CPASYNC16(smem_u32(Sb + col*(B_PADH*2) + ch*16), Bg + (size_t)col*NB + m0 + ch*8);
        }
    };

    load_stage(0, 0);       CP_COMMIT();
    load_stage(1, BKK);     CP_COMMIT();
    load_stage(2, 2*BKK);   CP_COMMIT();

    float acc[4][8][4];
#pragma unroll
    for (int mi = 0; mi < 4; ++mi)
#pragma unroll
        for (int ni = 0; ni < 8; ++ni)
#pragma unroll
            for (int q = 0; q < 4; ++q) acc[mi][ni][q] = 0.f;

    const int nb0 = warp_m * 64;
    const int cb0 = warp_n * 64;
    const int r4  = lane >> 2;   // 0..7
    const int l4  = lane & 3;    // 0..3

    int buf = 0;
    for (int it = 0; it < NSTEPS; ++it) {
        asm volatile("cp.async.wait_group 2;" ::: "memory");
        __syncthreads();
        const float*  As  = (const float*)(smc + buf * STAGE_BYTES);
        const __half* Bsh = (const __half*)(smc + buf * STAGE_BYTES + AS_BYTES);
#pragma unroll
        for (int ks = 0; ks < 2; ++ks) {
            const int kk = ks * 16;
            // A fragments: A[n][k=m], rows of As are m, cols are n
            const float* Ar = As + (kk + 2*l4)*A_PAD + nb0 + r4;
            uint32_t a[4][4];
#pragma unroll
            for (int mi = 0; mi < 4; ++mi) {
                const int cofs = mi*16;
                a[mi][0] = packh(Ar[cofs          ], Ar[cofs + A_PAD    ]);
                a[mi][1] = packh(Ar[cofs + 8      ], Ar[cofs + A_PAD + 8]);
                a[mi][2] = packh(Ar[cofs + 8*A_PAD], Ar[cofs + 9*A_PAD    ]);
                a[mi][3] = packh(Ar[cofs + 8*A_PAD + 8], Ar[cofs + 9*A_PAD + 8]);
            }
            // B fragments: Bsh[col][m], k-pair m-contiguous -> single b32
            const __half* Br = Bsh + kk + 2*l4;
            uint32_t b[8][2];
#pragma unroll
            for (int ni = 0; ni < 8; ++ni) {
                const int cc = cb0 + ni*8 + r4;
                b[ni][0] = *(const uint32_t*)(Br + cc*B_PADH);
                b[ni][1] = *(const uint32_t*)(Br + cc*B_PADH + 8);
            }
#pragma unroll
            for (int mi = 0; mi < 4; ++mi)
#pragma unroll
                for (int ni = 0; ni < 8; ++ni)
                    mma_f16(acc[mi][ni], a[mi], b[ni]);
        }
        __syncthreads();
        if (it + 3 < NSTEPS) load_stage(buf, (it + 3) * BKK);
        CP_COMMIT();
        buf = (buf == 2) ? 0 : buf + 1;
    }

    // ---- epilogue: per-k partials
    float* P = g_part + (size_t)kb*NB*COLS;
#pragma unroll
    for (int mi = 0; mi < 4; ++mi) {
        const int row0 = n0 + nb0 + mi*16 + r4;
#pragma unroll
        for (int ni = 0; ni < 8; ++ni) {
            const int col = c0 + cb0 + ni*8 + 2*l4;
            *(float2*)&P[(size_t) row0      *COLS + col] = make_float2(acc[mi][ni][0], acc[mi][ni][1]);
            *(float2*)&P[(size_t)(row0 + 8) *COLS + col] = make_float2(acc[mi][ni][2], acc[mi][ni][3]);
        }
    }
}

// ---------------------------------------------------------------------------
// out = relu( sum_kb g_part ), vectorized float4
// ---------------------------------------------------------------------------
__global__ void relu_sum_kernel(float4* __restrict__ out) {
    int idx = blockIdx.x * blockDim.x + threadIdx.x;      // 0 .. OUT_ELEMS/4
    if (idx < OUT_ELEMS/4) {
        int b  = idx / (NB*48);
        int r  = idx % (NB*48);
        int n  = r / 48;
        int c4 = r % 48;
        const float4* p = (const float4*)g_part;
        size_t off = (size_t)n*96 + b*48 + c4;
        float4 v0 = p[off];
        float4 v1 = p[(size_t)NB*96 + off];
        float4 v2 = p[2*(size_t)NB*96 + off];
        float4 o;
        o.x = fmaxf(v0.x + v1.x + v2.x, 0.f);
        o.y = fmaxf(v0.y + v1.y + v2.y, 0.f);
        o.z = fmaxf(v0.z + v1.z + v2.z, 0.f);
        o.w = fmaxf(v0.w + v1.w + v2.w, 0.f);
        out[idx] = o;
    }
}

// ---------------------------------------------------------------------------
extern "C" void kernel_launch(void* const* d_in, const int* in_sizes, int n_in,
                              void* d_out, int out_size) {
    const float* x     = (const float*)d_in[0];
    const float* cheb  = (const float*)d_in[1];
    const float* xj    = (const float*)d_in[2];
    const float* Gamma = (const float*)d_in[3];

    cudaFuncSetAttribute(gemm_kernel, cudaFuncAttributeMaxDynamicSharedMemorySize, SMEM_BYTES);

    lhs_kernel<<<3, 256>>>(Gamma, xj);
    zT_kernel<<<dim3(32, 12, 2), 128>>>(x);
    gemm_kernel<<<dim3(32, 3, 3), 128, SMEM_BYTES>>>(cheb);
    relu_sum_kernel<<<(OUT_ELEMS/4 + 255)/256, 256>>>((float4*)d_out);
}

// round 6
// speedup vs baseline: 1.5147x; 1.0918x over previous
#include <cuda_runtime.h>
#include <cuda_fp16.h>
#include <cstdint>

#define NB    4096
#define KCH   3
#define FIN   16
#define FOUT  16
#define TT    12
#define BATCH 2
#define COLS  384                       /* BATCH*FOUT*TT */
#define OUT_ELEMS (BATCH*NB*FOUT*TT)    /* 1572864 */

#define BM 128
#define BN 128
#define BKK 32
#define NSTEPS (NB/BKK)                 /* 128 */
#define A_PAD 132                       /* floats per A smem row */
#define B_PADH 40                       /* halves per B smem row */
#define AS_BYTES (BKK*A_PAD*4)          /* 16896 */
#define BS_BYTES (BN*B_PADH*2)          /* 10240 */
#define STAGE_BYTES (AS_BYTES + BS_BYTES) /* 27136 */
#define STAGES 4
#define SMEM_BYTES (STAGES*STAGE_BYTES)   /* 108544 */

__device__ float  g_lhs[KCH*FIN*FOUT];
__device__ __half g_zTh[(size_t)KCH*COLS*NB];   // [k][col][m], m contiguous, fp16
__device__ float  g_part[(size_t)KCH*NB*COLS];  // [k][n][col]

// ---------------------------------------------------------------------------
__device__ __forceinline__ uint32_t smem_u32(const void* p) {
    uint32_t a;
    asm("{ .reg .u64 t; cvta.to.shared.u64 t, %1; cvt.u32.u64 %0, t; }" : "=r"(a) : "l"(p));
    return a;
}
#define CPASYNC16(d, s) asm volatile("cp.async.cg.shared.global [%0], [%1], 16;" :: "r"(d), "l"(s) : "memory")
#define CP_COMMIT()     asm volatile("cp.async.commit_group;" ::: "memory")

__device__ __forceinline__ void mma_f16(float* c, const uint32_t* a, const uint32_t* b) {
    asm volatile(
        "mma.sync.aligned.m16n8k16.row.col.f32.f16.f16.f32 "
        "{%0,%1,%2,%3}, {%4,%5,%6,%7}, {%8,%9}, {%0,%1,%2,%3};"
        : "+f"(c[0]), "+f"(c[1]), "+f"(c[2]), "+f"(c[3])
        : "r"(a[0]), "r"(a[1]), "r"(a[2]), "r"(a[3]), "r"(b[0]), "r"(b[1]));
}
__device__ __forceinline__ uint32_t packh(float lo, float hi) {
    uint32_t r;
    asm("cvt.rn.f16x2.f32 %0, %1, %2;" : "=r"(r) : "f"(hi), "f"(lo));
    return r;
}

// ---------------------------------------------------------------------------
// lhs[k,f,o] = 0.5 * sum_j Gamma[j,f,o] * xj[j,k]
// ---------------------------------------------------------------------------
__global__ void lhs_kernel(const float* __restrict__ Gamma, const float* __restrict__ xj) {
    int idx = blockIdx.x * blockDim.x + threadIdx.x;
    if (idx < KCH*FIN*FOUT) {
        int k = idx / (FIN*FOUT), fo = idx % (FIN*FOUT);
        float s = 0.f;
#pragma unroll
        for (int j = 0; j < KCH; ++j) s += Gamma[j*FIN*FOUT + fo] * xj[j*KCH + k];
        g_lhs[idx] = 0.5f * s;
    }
}

// ---------------------------------------------------------------------------
// zTh[k][col=b*192+o*12+t][m] = fp16( sum_f x[b,m,f,t] * lhs[k,f,o] )
// ---------------------------------------------------------------------------
__global__ void zT_kernel(const float* __restrict__ x) {
    __shared__ float ls[KCH*FIN*FOUT];
    const int tid = threadIdx.x;
    const int mc = blockIdx.x, t = blockIdx.y, b = blockIdx.z;
    for (int i = tid; i < KCH*FIN*FOUT; i += 128) ls[i] = g_lhs[i];
    __syncthreads();
    const int m = mc * 128 + tid;
    float xv[FIN];
    const float* xp = x + ((size_t)(b*NB + m) * FIN) * TT + t;
#pragma unroll
    for (int f = 0; f < FIN; ++f) xv[f] = xp[f*TT];
#pragma unroll
    for (int k = 0; k < KCH; ++k)
#pragma unroll
        for (int o = 0; o < FOUT; ++o) {
            float s = 0.f;
#pragma unroll
            for (int f = 0; f < FIN; ++f) s += xv[f] * ls[(k*FIN + f)*FOUT + o];
            g_zTh[((size_t)k*COLS + b*(FOUT*TT) + o*TT + t) * NB + m] = __float2half_rn(s);
        }
}

// ---------------------------------------------------------------------------
// GEMM: g_part[kb][n][col] = sum_m cheb[kb][m][n] * zTh[kb][col][m]
// fp16 mma.sync m16n8k16, 128x128x32 tile, 64x64 warp tile, 4-stage cp.async,
// single __syncthreads per iteration.
// ---------------------------------------------------------------------------
__global__ void __launch_bounds__(128, 2) gemm_kernel(const float* __restrict__ cheb) {
    extern __shared__ char smc[];
    const int tid  = threadIdx.x;
    const int lane = tid & 31, wid = tid >> 5;
    const int warp_m = wid >> 1, warp_n = wid & 1;      // 2x2 warp grid
    const int n0 = blockIdx.x * BM;
    const int c0 = blockIdx.y * BN;
    const int kb = blockIdx.z;

    const float*  Ag = cheb  + (size_t)kb*NB*NB + n0;              // + m*NB
    const __half* Bg = g_zTh + (size_t)kb*COLS*NB + (size_t)c0*NB; // + col*NB + m

    auto load_stage = [&](int stage, int m0) {
        char* Sa = smc + stage * STAGE_BYTES;
        char* Sb = Sa + AS_BYTES;
#pragma unroll
        for (int j = 0; j < 8; ++j) {
            int i = tid + 128*j;
            int m = i >> 5, c = i & 31;                  // c: 16B chunk (4 floats)
            CPASYNC16(smem_u32(Sa + (m*A_PAD + c*4)*4), Ag + (size_t)(m0 + m)*NB + c*4);
        }
#pragma unroll
        for (int j = 0; j < 4; ++j) {
            int i = tid + 128*j;
            int col = i >> 2, ch = i & 3;                // ch: 16B chunk (8 halves)
            CPASYNC16(smem_u32(Sb + col*(B_PADH*2) + ch*16), Bg + (size_t)col*NB + m0 + ch*8);
        }
    };

    load_stage(0, 0);       CP_COMMIT();
    load_stage(1, BKK);     CP_COMMIT();
    load_stage(2, 2*BKK);   CP_COMMIT();

    float acc[4][8][4];
#pragma unroll
    for (int mi = 0; mi < 4; ++mi)
#pragma unroll
        for (int ni = 0; ni < 8; ++ni)
#pragma unroll
            for (int q = 0; q < 4; ++q) acc[mi][ni][q] = 0.f;

    const int nb0 = warp_m * 64;
    const int cb0 = warp_n * 64;
    const int r4  = lane >> 2;   // 0..7
    const int l4  = lane & 3;    // 0..3

    for (int it = 0; it < NSTEPS; ++it) {
        const int buf = it & 3;
        asm volatile("cp.async.wait_group 2;" ::: "memory");
        __syncthreads();
        const float*  As  = (const float*)(smc + buf * STAGE_BYTES);
        const __half* Bsh = (const __half*)(smc + buf * STAGE_BYTES + AS_BYTES);
#pragma unroll
        for (int ks = 0; ks < 2; ++ks) {
            const int kk = ks * 16;
            const float* Ar = As + (kk + 2*l4)*A_PAD + nb0 + r4;
            uint32_t a[4][4];
#pragma unroll
            for (int mi = 0; mi < 4; ++mi) {
                const int cofs = mi*16;
                a[mi][0] = packh(Ar[cofs              ], Ar[cofs + A_PAD      ]);
                a[mi][1] = packh(Ar[cofs + 8          ], Ar[cofs + A_PAD + 8  ]);
                a[mi][2] = packh(Ar[cofs + 8*A_PAD    ], Ar[cofs + 9*A_PAD    ]);
                a[mi][3] = packh(Ar[cofs + 8*A_PAD + 8], Ar[cofs + 9*A_PAD + 8]);
            }
            const __half* Br = Bsh + kk + 2*l4;
            uint32_t b[8][2];
#pragma unroll
            for (int ni = 0; ni < 8; ++ni) {
                const int cc = cb0 + ni*8 + r4;
                b[ni][0] = *(const uint32_t*)(Br + cc*B_PADH);
                b[ni][1] = *(const uint32_t*)(Br + cc*B_PADH + 8);
            }
#pragma unroll
            for (int mi = 0; mi < 4; ++mi)
#pragma unroll
                for (int ni = 0; ni < 8; ++ni)
                    mma_f16(acc[mi][ni], a[mi], b[ni]);
        }
        // stage (it+3)&3 == (it-1)&3 was fully consumed before the barrier above
        if (it + 3 < NSTEPS) load_stage((it + 3) & 3, (it + 3) * BKK);
        CP_COMMIT();
    }

    // ---- epilogue: per-k partials
    float* P = g_part + (size_t)kb*NB*COLS;
#pragma unroll
    for (int mi = 0; mi < 4; ++mi) {
        const int row0 = n0 + nb0 + mi*16 + r4;
#pragma unroll
        for (int ni = 0; ni < 8; ++ni) {
            const int col = c0 + cb0 + ni*8 + 2*l4;
            *(float2*)&P[(size_t) row0      *COLS + col] = make_float2(acc[mi][ni][0], acc[mi][ni][1]);
            *(float2*)&P[(size_t)(row0 + 8) *COLS + col] = make_float2(acc[mi][ni][2], acc[mi][ni][3]);
        }
    }
}

// ---------------------------------------------------------------------------
// out = relu( sum_kb g_part ), vectorized float4
// ---------------------------------------------------------------------------
__global__ void relu_sum_kernel(float4* __restrict__ out) {
    int idx = blockIdx.x * blockDim.x + threadIdx.x;      // 0 .. OUT_ELEMS/4
    if (idx < OUT_ELEMS/4) {
        int b  = idx / (NB*48);
        int r  = idx % (NB*48);
        int n  = r / 48;
        int c4 = r % 48;
        const float4* p = (const float4*)g_part;
        size_t off = (size_t)n*96 + b*48 + c4;
        float4 v0 = p[off];
        float4 v1 = p[(size_t)NB*96 + off];
        float4 v2 = p[2*(size_t)NB*96 + off];
        float4 o;
        o.x = fmaxf(v0.x + v1.x + v2.x, 0.f);
        o.y = fmaxf(v0.y + v1.y + v2.y, 0.f);
        o.z = fmaxf(v0.z + v1.z + v2.z, 0.f);
        o.w = fmaxf(v0.w + v1.w + v2.w, 0.f);
        out[idx] = o;
    }
}

// ---------------------------------------------------------------------------
extern "C" void kernel_launch(void* const* d_in, const int* in_sizes, int n_in,
                              void* d_out, int out_size) {
    const float* x     = (const float*)d_in[0];
    const float* cheb  = (const float*)d_in[1];
    const float* xj    = (const float*)d_in[2];
    const float* Gamma = (const float*)d_in[3];

    cudaFuncSetAttribute(gemm_kernel, cudaFuncAttributeMaxDynamicSharedMemorySize, SMEM_BYTES);

    lhs_kernel<<<3, 256>>>(Gamma, xj);
    zT_kernel<<<dim3(32, 12, 2), 128>>>(x);
    gemm_kernel<<<dim3(32, 3, 3), 128, SMEM_BYTES>>>(cheb);
    relu_sum_kernel<<<(OUT_ELEMS/4 + 255)/256, 256>>>((float4*)d_out);
}